// round 12
// baseline (speedup 1.0000x reference)
#include <cuda_runtime.h>
#include <cuda_bf16.h>
#include <math.h>
#include <stdint.h>

#define BB 4
#define SS 2048
#define HH 16
#define DD 128
#define DH 64    // effective qk dim (first half, duplicated in reference)
#define BM 128
#define BN 64
#define NTHR 512

typedef unsigned long long u64;

// ---- scratch (no allocs allowed) ----
__device__ float g_Qp[BB*HH*DH*SS];                  // [b,h,kdim,s]  33.5 MB
__device__ float g_Kp[BB*HH*DH*SS];                  // [b,h,kdim,s]  33.5 MB
__device__ __nv_bfloat16 g_Vhi[(size_t)BB*HH*SS*DD]; // [b,h,s,d]     33.5 MB
__device__ __nv_bfloat16 g_Vlo[(size_t)BB*HH*SS*DD]; // [b,h,s,d]     33.5 MB
__device__ float g_inv[DH];

// ---- smem layout (bytes) ----
#define OFF_QST 0            // fp32 Q [64 kdim][128 m]          32768
#define OFF_KS  32768        // fp32 K 2 x [64 kdim][64 n]       32768
#define OFF_VHI 65536        // bf16 Vhi 2 x [64 k][128 d]       34816 (row 272B)
#define OFF_VLO 100352       // bf16 Vlo 2 x                     34816
#define OFF_PHI 135168       // bf16 P  2 x (hi 18432 + lo 18432) = 73728
#define OFF_F   208896       // float f 2 x 128
#define OFF_L   209920       // float l[128]
#define SMEM_TOTAL 210432
#define VROWB 272            // ≡ 4 words mod 32 banks -> conflict-free ldmatrix
#define VTILE 17408          // 64 * 272 (per split per buffer)
#define VLO_DELTA 34816      // OFF_VLO - OFF_VHI
#define PROWB 144            // ≡ 4 words mod 32
#define PBUF 36864           // per P buffer (hi+lo)
#define PLO_DELTA 18432

// ---------------- packed f32x2 helpers (GEMM1) ----------------
__device__ __forceinline__ u64 bcast2(float x) {
    u64 r; asm("mov.b64 %0, {%1, %1};" : "=l"(r) : "f"(x)); return r;
}
__device__ __forceinline__ void ffma2(u64& d, u64 a, u64 b) {
    asm("fma.rn.f32x2 %0, %1, %2, %3;" : "=l"(d) : "l"(a), "l"(b), "l"(d));
}
__device__ __forceinline__ void unpack2(u64 v, float& lo, float& hi) {
    asm("mov.b64 {%0, %1}, %2;" : "=f"(lo), "=f"(hi) : "l"(v));
}

// ---------------- cp.async ----------------
__device__ __forceinline__ void cp_async16(uint32_t saddr, const void* gptr) {
    asm volatile("cp.async.cg.shared.global [%0], [%1], 16;" :: "r"(saddr), "l"(gptr));
}
__device__ __forceinline__ void cp_commit() { asm volatile("cp.async.commit_group;"); }
__device__ __forceinline__ void cp_wait_all() { asm volatile("cp.async.wait_group 0;"); }
__device__ __forceinline__ void cp_wait_1()  { asm volatile("cp.async.wait_group 1;"); }

// ---------------- tensor core: ldmatrix + mma.sync (base PTX) ----------------
__device__ __forceinline__ void ldmx4(uint32_t* r, uint32_t a) {
    asm volatile("ldmatrix.sync.aligned.m8n8.x4.shared.b16 {%0,%1,%2,%3}, [%4];"
        : "=r"(r[0]), "=r"(r[1]), "=r"(r[2]), "=r"(r[3]) : "r"(a));
}
__device__ __forceinline__ void ldmx4t(uint32_t* r, uint32_t a) {
    asm volatile("ldmatrix.sync.aligned.m8n8.x4.trans.shared.b16 {%0,%1,%2,%3}, [%4];"
        : "=r"(r[0]), "=r"(r[1]), "=r"(r[2]), "=r"(r[3]) : "r"(a));
}
__device__ __forceinline__ void mma16816(float* c, const uint32_t* a, const uint32_t* b) {
    asm volatile("mma.sync.aligned.m16n8k16.row.col.f32.bf16.bf16.f32 "
        "{%0,%1,%2,%3}, {%4,%5,%6,%7}, {%8,%9}, {%0,%1,%2,%3};"
        : "+f"(c[0]), "+f"(c[1]), "+f"(c[2]), "+f"(c[3])
        : "r"(a[0]), "r"(a[1]), "r"(a[2]), "r"(a[3]), "r"(b[0]), "r"(b[1]));
}

// ---------------- prep ----------------
__global__ void init_inv() {
    int i = threadIdx.x;
    g_inv[i] = (float)exp(-(double)i * (9.210340371976184 / 64.0)); // ln(1e4)/64
}

__global__ void prep_qk(const float* __restrict__ q, const float* __restrict__ k) {
    __shared__ float qs[64*65];
    __shared__ float ks[64*65];
    const int st = blockIdx.x, h = blockIdx.y, b = blockIdx.z;
    const int tid = threadIdx.x;
    for (int idx = tid; idx < 64*64; idx += 256) {
        int sl = idx >> 6, i = idx & 63;
        int s = st*64 + sl;
        float fc = 2.0f * ((float)s * g_inv[i]);
        size_t gin = ((size_t)(b*SS + s)*HH + h)*DD + i;
        qs[i*65 + sl] = q[gin] * fc;
        ks[i*65 + sl] = k[gin] * fc;
    }
    __syncthreads();
    float* Qo = g_Qp + (size_t)((b*HH + h)*DH)*SS + st*64;
    float* Ko = g_Kp + (size_t)((b*HH + h)*DH)*SS + st*64;
    for (int idx = tid; idx < 64*64; idx += 256) {
        int i = idx >> 6, sl = idx & 63;
        Qo[(size_t)i*SS + sl] = qs[i*65 + sl];
        Ko[(size_t)i*SS + sl] = ks[i*65 + sl];
    }
}

__global__ void prep_v(const float* __restrict__ v) {
    const int st = blockIdx.x, h = blockIdx.y, b = blockIdx.z;
    const int tid = threadIdx.x;
    for (int idx = tid; idx < 64*32; idx += 256) {
        int s = idx >> 5, d4 = idx & 31;
        float4 x = *(const float4*)&v[((size_t)(b*SS + st*64 + s)*HH + h)*DD + d4*4];
        __nv_bfloat16 h0 = __float2bfloat16(x.x), h1 = __float2bfloat16(x.y);
        __nv_bfloat16 h2 = __float2bfloat16(x.z), h3 = __float2bfloat16(x.w);
        __nv_bfloat16 l0 = __float2bfloat16(x.x - __bfloat162float(h0));
        __nv_bfloat16 l1 = __float2bfloat16(x.y - __bfloat162float(h1));
        __nv_bfloat16 l2 = __float2bfloat16(x.z - __bfloat162float(h2));
        __nv_bfloat16 l3 = __float2bfloat16(x.w - __bfloat162float(h3));
        size_t o = ((size_t)(b*HH + h)*SS + st*64 + s)*DD + d4*4;
        __nv_bfloat162* ph = (__nv_bfloat162*)(g_Vhi + o);
        __nv_bfloat162* pl = (__nv_bfloat162*)(g_Vlo + o);
        __nv_bfloat162 a; a.x = h0; a.y = h1; ph[0] = a;
        a.x = h2; a.y = h3; ph[1] = a;
        a.x = l0; a.y = l1; pl[0] = a;
        a.x = l2; a.y = l3; pl[1] = a;
    }
}

// ---------------- attn building blocks ----------------
__device__ __forceinline__ void gemm1_chunk(const float* QsT, const float* KsT,
                                            int ti, int tj, int ks, u64 acc2[4][4]) {
    #pragma unroll
    for (int i = 0; i < 16; i++) {
        int kk = ks*16 + i;
        ulonglong2 a01 = *(const ulonglong2*)&QsT[(kk << 7) + (ti << 3)];
        ulonglong2 a23 = *(const ulonglong2*)&QsT[(kk << 7) + (ti << 3) + 4];
        float4 b4 = *(const float4*)&KsT[(kk << 6) + (tj << 2)];
        u64 b0 = bcast2(b4.x), b1 = bcast2(b4.y);
        u64 b2 = bcast2(b4.z), b3 = bcast2(b4.w);
        ffma2(acc2[0][0], a01.x, b0); ffma2(acc2[0][1], a01.x, b1);
        ffma2(acc2[0][2], a01.x, b2); ffma2(acc2[0][3], a01.x, b3);
        ffma2(acc2[1][0], a01.y, b0); ffma2(acc2[1][1], a01.y, b1);
        ffma2(acc2[1][2], a01.y, b2); ffma2(acc2[1][3], a01.y, b3);
        ffma2(acc2[2][0], a23.x, b0); ffma2(acc2[2][1], a23.x, b1);
        ffma2(acc2[2][2], a23.x, b2); ffma2(acc2[2][3], a23.x, b3);
        ffma2(acc2[3][0], a23.y, b0); ffma2(acc2[3][1], a23.y, b1);
        ffma2(acc2[3][2], a23.y, b2); ffma2(acc2[3][3], a23.y, b3);
    }
}

// GEMM2 chunk for one ks (k16): warp covers 32 rows (2 m-tiles) x 64 d (its half)
__device__ __forceinline__ void gemm2_chunk(uint32_t pa, uint32_t vb, int ks, float* c) {
    uint32_t ko = (uint32_t)(ks*16)*VROWB;
    uint32_t ahi0[4], alo0[4], ahi1[4], alo1[4];
    ldmx4(ahi0, pa + ks*32);
    ldmx4(alo0, pa + PLO_DELTA + ks*32);
    ldmx4(ahi1, pa + 16*PROWB + ks*32);
    ldmx4(alo1, pa + PLO_DELTA + 16*PROWB + ks*32);
    #pragma unroll
    for (int nb = 0; nb < 4; nb++) {
        uint32_t bh[4], bl[4];
        ldmx4t(bh, vb + ko + nb*32);
        ldmx4t(bl, vb + VLO_DELTA + ko + nb*32);
        mma16816(&c[(2*nb)*4],          ahi0, bh);
        mma16816(&c[(2*nb)*4],          ahi0, bl);
        mma16816(&c[(2*nb)*4],          alo0, bh);
        mma16816(&c[(2*nb + 1)*4],      ahi0, bh + 2);
        mma16816(&c[(2*nb + 1)*4],      ahi0, bl + 2);
        mma16816(&c[(2*nb + 1)*4],      alo0, bh + 2);
        mma16816(&c[(8 + 2*nb)*4],      ahi1, bh);
        mma16816(&c[(8 + 2*nb)*4],      ahi1, bl);
        mma16816(&c[(8 + 2*nb)*4],      alo1, bh);
        mma16816(&c[(8 + 2*nb + 1)*4],  ahi1, bh + 2);
        mma16816(&c[(8 + 2*nb + 1)*4],  ahi1, bl + 2);
        mma16816(&c[(8 + 2*nb + 1)*4],  alo1, bh + 2);
    }
}

__device__ __forceinline__ void rescale_c(float* c, const float* fprev, int rg, int lane) {
    #pragma unroll
    for (int mt = 0; mt < 2; mt++) {
        float f0 = fprev[rg*32 + mt*16 + (lane >> 2)];
        float f1 = fprev[rg*32 + mt*16 + (lane >> 2) + 8];
        #pragma unroll
        for (int nt = 0; nt < 8; nt++) {
            c[(mt*8 + nt)*4 + 0] *= f0; c[(mt*8 + nt)*4 + 1] *= f0;
            c[(mt*8 + nt)*4 + 2] *= f1; c[(mt*8 + nt)*4 + 3] *= f1;
        }
    }
}

__device__ __forceinline__ void softmax_tile(u64 acc2[4][4], float* mrow, float* lrow,
                                             char* smem, uint32_t phi_off, float* fptr,
                                             int ti, int tj) {
    float p[8][4];
    #pragma unroll
    for (int mp = 0; mp < 4; mp++)
        #pragma unroll
        for (int n = 0; n < 4; n++)
            unpack2(acc2[mp][n], p[2*mp][n], p[2*mp + 1][n]);

    const float sc2 = 1.44269504088896340736f / 64.0f;  // log2(e)/64

    float mx[8];
    #pragma unroll
    for (int r = 0; r < 8; r++)
        mx[r] = fmaxf(fmaxf(p[r][0], p[r][1]), fmaxf(p[r][2], p[r][3]));
    #pragma unroll
    for (int st = 1; st < 16; st <<= 1)
        #pragma unroll
        for (int r = 0; r < 8; r++)
            mx[r] = fmaxf(mx[r], __shfl_xor_sync(0xffffffffu, mx[r], st));

    float fr[8];
    #pragma unroll
    for (int r = 0; r < 8; r++) {
        float mn = fmaxf(mrow[r], mx[r]*sc2);
        fr[r] = exp2f(mrow[r] - mn);   // 0 on first tile
        mrow[r] = mn;
    }

    float sr[8];
    #pragma unroll
    for (int r = 0; r < 8; r++) {
        #pragma unroll
        for (int cx = 0; cx < 4; cx++)
            p[r][cx] = exp2f(fmaf(p[r][cx], sc2, -mrow[r]));
        sr[r] = (p[r][0] + p[r][1]) + (p[r][2] + p[r][3]);

        int rr = ti*8 + r;
        __nv_bfloat16 h0 = __float2bfloat16(p[r][0]), h1 = __float2bfloat16(p[r][1]);
        __nv_bfloat16 h2 = __float2bfloat16(p[r][2]), h3 = __float2bfloat16(p[r][3]);
        __nv_bfloat162 hh01; hh01.x = h0; hh01.y = h1;
        __nv_bfloat162 hh23; hh23.x = h2; hh23.y = h3;
        __nv_bfloat162 ll01, ll23;
        ll01.x = __float2bfloat16(p[r][0] - __bfloat162float(h0));
        ll01.y = __float2bfloat16(p[r][1] - __bfloat162float(h1));
        ll23.x = __float2bfloat16(p[r][2] - __bfloat162float(h2));
        ll23.y = __float2bfloat16(p[r][3] - __bfloat162float(h3));
        *(uint2*)(smem + phi_off + rr*PROWB + tj*8) =
            make_uint2(*(uint32_t*)&hh01, *(uint32_t*)&hh23);
        *(uint2*)(smem + phi_off + PLO_DELTA + rr*PROWB + tj*8) =
            make_uint2(*(uint32_t*)&ll01, *(uint32_t*)&ll23);
        if (tj == 0) fptr[rr] = fr[r];
    }
    #pragma unroll
    for (int st = 1; st < 16; st <<= 1)
        #pragma unroll
        for (int r = 0; r < 8; r++)
            sr[r] += __shfl_xor_sync(0xffffffffu, sr[r], st);
    #pragma unroll
    for (int r = 0; r < 8; r++)
        lrow[r] = lrow[r]*fr[r] + sr[r];
}

// ---------------- warp-specialized flash attention ----------------
// 512 threads / 16 warps. WG-A (warps 0-7): GEMM1 + softmax -> P/f.
// WG-B (warps 8-15): HMMA GEMM2 one tile behind. All threads share loads/barriers.
__global__ __launch_bounds__(NTHR, 1)
void attn_kernel(float* __restrict__ out) {
    extern __shared__ char smem[];
    const uint32_t sbase = (uint32_t)__cvta_generic_to_shared(smem);
    float* QsT = (float*)(smem + OFF_QST);
    float* lptr = (float*)(smem + OFF_L);

    const int qt = blockIdx.x, h = blockIdx.y, b = blockIdx.z;
    const int tid = threadIdx.x;
    const int wid = tid >> 5, lane = tid & 31;
    const bool isA = (wid < 8);
    const int ti = (tid & 255) >> 4, tj = tid & 15;   // WG-A layout
    const int bwid = wid - 8;                          // WG-B warp 0..7
    const int rg = bwid & 3, dh = bwid >> 2;

    const float* Qg  = g_Qp + (size_t)((b*HH + h)*DH)*SS + qt*BM;
    const float* Kg0 = g_Kp + (size_t)((b*HH + h)*DH)*SS;
    const __nv_bfloat16* Vh0 = g_Vhi + (size_t)(b*HH + h)*SS*DD;
    const __nv_bfloat16* Vl0 = g_Vlo + (size_t)(b*HH + h)*SS*DD;

    // warp-fixed GEMM2 base addresses (WG-B only; harmless for A)
    const uint32_t pa_base = sbase + OFF_PHI + (uint32_t)(rg*32 + (lane & 15))*PROWB
                           + ((lane >> 4) << 4);
    const uint32_t vb_base = sbase + OFF_VHI + (uint32_t)(lane & 15)*VROWB
                           + ((lane >> 4) << 4) + (uint32_t)dh*128;

    // ---- prologue: Q + K0 + V0 (all 512 threads) ----
    #pragma unroll
    for (int it = 0; it < 4; it++) {
        int idx4 = tid + it*NTHR;
        int kk = idx4 >> 5, m4 = idx4 & 31;
        cp_async16(sbase + OFF_QST + (uint32_t)idx4*16, Qg + (size_t)kk*SS + m4*4);
    }
    #pragma unroll
    for (int it = 0; it < 2; it++) {
        int idx4 = tid + it*NTHR;
        int kk = idx4 >> 4, n4 = idx4 & 15;
        cp_async16(sbase + OFF_KS + (uint32_t)idx4*16, Kg0 + (size_t)kk*SS + n4*4);
    }
    #pragma unroll
    for (int it = 0; it < 2; it++) {
        int idx = tid + it*NTHR;
        int row = idx >> 4, cc = idx & 15;
        cp_async16(sbase + OFF_VHI + (uint32_t)row*VROWB + cc*16, Vh0 + (size_t)row*DD + cc*8);
        cp_async16(sbase + OFF_VLO + (uint32_t)row*VROWB + cc*16, Vl0 + (size_t)row*DD + cc*8);
    }
    cp_commit();

    float mrow[8], lrow[8];       // WG-A state
    #pragma unroll
    for (int r = 0; r < 8; r++) { mrow[r] = -INFINITY; lrow[r] = 0.0f; }

    float c[64];                  // WG-B state
    #pragma unroll
    for (int i = 0; i < 64; i++) c[i] = 0.0f;

    // ---- peel kt = 0 ----
    cp_wait_all();
    __syncthreads();
    {   // prefetch K1
        const float* Kg = Kg0 + BN;
        uint32_t kd = sbase + OFF_KS + 16384;
        #pragma unroll
        for (int it = 0; it < 2; it++) {
            int idx4 = tid + it*NTHR;
            int kk = idx4 >> 4, n4 = idx4 & 15;
            cp_async16(kd + (uint32_t)idx4*16, Kg + (size_t)kk*SS + n4*4);
        }
        cp_commit();
    }
    if (isA) {
        u64 acc2[4][4];
        #pragma unroll
        for (int mp = 0; mp < 4; mp++)
            #pragma unroll
            for (int n = 0; n < 4; n++) acc2[mp][n] = 0ULL;
        #pragma unroll
        for (int ks = 0; ks < 4; ks++)
            gemm1_chunk(QsT, (const float*)(smem + OFF_KS), ti, tj, ks, acc2);
        softmax_tile(acc2, mrow, lrow, smem, OFF_PHI, (float*)(smem + OFF_F), ti, tj);
    }
    {   // prefetch V1 (buffer 1 free; no barrier needed on first tile)
        const __nv_bfloat16* Vh = Vh0 + (size_t)BN*DD;
        const __nv_bfloat16* Vl = Vl0 + (size_t)BN*DD;
        #pragma unroll
        for (int it = 0; it < 2; it++) {
            int idx = tid + it*NTHR;
            int row = idx >> 4, cc = idx & 15;
            cp_async16(sbase + OFF_VHI + VTILE + (uint32_t)row*VROWB + cc*16,
                       Vh + (size_t)row*DD + cc*8);
            cp_async16(sbase + OFF_VLO + VTILE + (uint32_t)row*VROWB + cc*16,
                       Vl + (size_t)row*DD + cc*8);
        }
        cp_commit();
    }

    // ---- main loop: kt = 1..31; WG-B works on tile kt-1 ----
    for (int kt = 1; kt < SS/BN; ++kt) {
        cp_wait_1();         // K[kt] + V[kt-1] done; newest group V[kt] may fly
        __syncthreads();     // orders P[kt-1]/f[kt-1] stores

        if (kt + 1 < SS/BN) {  // prefetch K[kt+1]
            const float* Kg = Kg0 + (kt + 1)*BN;
            uint32_t kd = sbase + OFF_KS + (uint32_t)((kt + 1) & 1)*16384;
            #pragma unroll
            for (int it = 0; it < 2; it++) {
                int idx4 = tid + it*NTHR;
                int kk = idx4 >> 4, n4 = idx4 & 15;
                cp_async16(kd + (uint32_t)idx4*16, Kg + (size_t)kk*SS + n4*4);
            }
        }
        cp_commit();

        if (isA) {
            const float* KsT = (const float*)(smem + OFF_KS + (uint32_t)(kt & 1)*16384);
            u64 acc2[4][4];
            #pragma unroll
            for (int mp = 0; mp < 4; mp++)
                #pragma unroll
                for (int n = 0; n < 4; n++) acc2[mp][n] = 0ULL;
            #pragma unroll
            for (int ks = 0; ks < 4; ks++)
                gemm1_chunk(QsT, KsT, ti, tj, ks, acc2);
            // stash acc2 -> softmax after mid-barrier (keeps V prefetch early)
            __syncthreads();   // WG-B done reading V[kt-1]
            // (prefetch below is issued by all threads between barriers)
            if (kt + 1 < SS/BN) {
                const __nv_bfloat16* Vh = Vh0 + (size_t)((kt + 1)*BN)*DD;
                const __nv_bfloat16* Vl = Vl0 + (size_t)((kt + 1)*BN)*DD;
                uint32_t vh = sbase + OFF_VHI + (uint32_t)((kt + 1) & 1)*VTILE;
                uint32_t vl = sbase + OFF_VLO + (uint32_t)((kt + 1) & 1)*VTILE;
                #pragma unroll
                for (int it = 0; it < 2; it++) {
                    int idx = tid + it*NTHR;
                    int row = idx >> 4, cc = idx & 15;
                    cp_async16(vh + (uint32_t)row*VROWB + cc*16, Vh + (size_t)row*DD + cc*8);
                    cp_async16(vl + (uint32_t)row*VROWB + cc*16, Vl + (size_t)row*DD + cc*8);
                }
            }
            cp_commit();
            softmax_tile(acc2, mrow, lrow, smem,
                         OFF_PHI + (uint32_t)(kt & 1)*PBUF,
                         (float*)(smem + OFF_F + (uint32_t)(kt & 1)*512), ti, tj);
        } else {
            const float* fprev = (const float*)(smem + OFF_F + (uint32_t)((kt - 1) & 1)*512);
            const uint32_t pa = pa_base + (uint32_t)((kt - 1) & 1)*PBUF;
            const uint32_t vb = vb_base + (uint32_t)((kt - 1) & 1)*VTILE;
            rescale_c(c, fprev, rg, lane);
            #pragma unroll
            for (int ks = 0; ks < 4; ks++)
                gemm2_chunk(pa, vb, ks, c);
            __syncthreads();   // matches WG-A's mid barrier
            if (kt + 1 < SS/BN) {
                const __nv_bfloat16* Vh = Vh0 + (size_t)((kt + 1)*BN)*DD;
                const __nv_bfloat16* Vl = Vl0 + (size_t)((kt + 1)*BN)*DD;
                uint32_t vh = sbase + OFF_VHI + (uint32_t)((kt + 1) & 1)*VTILE;
                uint32_t vl = sbase + OFF_VLO + (uint32_t)((kt + 1) & 1)*VTILE;
                #pragma unroll
                for (int it = 0; it < 2; it++) {
                    int idx = tid + it*NTHR;
                    int row = idx >> 4, cc = idx & 15;
                    cp_async16(vh + (uint32_t)row*VROWB + cc*16, Vh + (size_t)row*DD + cc*8);
                    cp_async16(vl + (uint32_t)row*VROWB + cc*16, Vl + (size_t)row*DD + cc*8);
                }
            }
            cp_commit();
        }
    }

    // ---- tail: GEMM2 for last tile (kt = 31) ----
    cp_wait_all();
    __syncthreads();   // P[31]/f[31] visible
    if (!isA) {
        const int lt = (SS/BN - 1) & 1;
        rescale_c(c, (const float*)(smem + OFF_F + (uint32_t)lt*512), rg, lane);
        const uint32_t pa = pa_base + (uint32_t)lt*PBUF;
        const uint32_t vb = vb_base + (uint32_t)lt*VTILE;
        #pragma unroll
        for (int ks = 0; ks < 4; ks++)
            gemm2_chunk(pa, vb, ks, c);
    }

    // ---- epilogue: WG-A publishes l, WG-B normalizes + stores ----
    if (isA && tj == 0) {
        #pragma unroll
        for (int r = 0; r < 8; r++) lptr[ti*8 + r] = lrow[r];
    }
    __syncthreads();
    if (!isA) {
        #pragma unroll
        for (int mt = 0; mt < 2; mt++) {
            int rloc = rg*32 + mt*16 + (lane >> 2);
            float il0 = 1.0f / lptr[rloc];
            float il1 = 1.0f / lptr[rloc + 8];
            int r0 = qt*BM + rloc;
            float* op0 = out + (((size_t)b*SS + r0)*HH + h)*DD + dh*64 + (lane & 3)*2;
            float* op1 = op0 + (size_t)8*HH*DD;   // row+8 -> s+8
            #pragma unroll
            for (int nt = 0; nt < 8; nt++) {
                int ci = (mt*8 + nt)*4;
                *(float2*)(op0 + nt*8) = make_float2(c[ci + 0]*il0, c[ci + 1]*il0);
                *(float2*)(op1 + nt*8) = make_float2(c[ci + 2]*il1, c[ci + 3]*il1);
            }
        }
    }
}

extern "C" void kernel_launch(void* const* d_in, const int* in_sizes, int n_in,
                              void* d_out, int out_size) {
    const float* q = (const float*)d_in[0];
    const float* k = (const float*)d_in[1];
    const float* v = (const float*)d_in[2];
    float* out = (float*)d_out;

    cudaFuncSetAttribute(attn_kernel, cudaFuncAttributeMaxDynamicSharedMemorySize, SMEM_TOTAL);

    init_inv<<<1, 64>>>();
    dim3 pgrid(SS/64, HH, BB);
    prep_qk<<<pgrid, 256>>>(q, k);
    prep_v<<<pgrid, 256>>>(v);

    dim3 grid(SS/BM, HH, BB);
    attn_kernel<<<grid, NTHR, SMEM_TOTAL>>>(out);
}